// round 1
// baseline (speedup 1.0000x reference)
#include <cuda_runtime.h>
#include <cstdint>
#include <cstddef>

#define SEQ 128
#define BATCH 64
#define EMB 1024
#define HID 1024
#define OUT_DIM 32000
#define VOCAB 32000
#define KCH 8            // split-K chunks in recurrence
#define KC_LEN (HID / KCH)

// ---------------- device scratch (no allocs allowed) ----------------
__device__ __align__(16) float g_xh[SEQ * BATCH * HID];     // 33.5 MB
__device__ __align__(16) float g_hall[SEQ * BATCH * HID];   // 33.5 MB
__device__ __align__(16) float g_h[BATCH * HID];            // 256 KB
__device__ __align__(16) float g_part[KCH * BATCH * HID];   // 2 MB
__device__ int g_idx[SEQ * BATCH];
__device__ int g_is64;

// ---------------- dtype sniff for x (int32 vs int64) ----------------
__global__ void k_sniff(const void* x) {
    __shared__ int bad;
    if (threadIdx.x == 0) bad = 0;
    __syncthreads();
    const unsigned long long* p = (const unsigned long long*)x;
    int mybad = 0;
    for (int i = threadIdx.x; i < 4096; i += 256) {   // 32KB: safe for both dtypes
        if (p[i] >= (unsigned long long)VOCAB) mybad = 1;
    }
    if (mybad) atomicOr(&bad, 1);
    __syncthreads();
    if (threadIdx.x == 0) g_is64 = bad ? 0 : 1;
}

__global__ void k_decode(const void* x) {
    int i = blockIdx.x * 256 + threadIdx.x;
    if (i >= SEQ * BATCH) return;
    if (g_is64) g_idx[i] = (int)((const long long*)x)[i];
    else        g_idx[i] = ((const int*)x)[i];
}

__global__ void k_copyh(const float* __restrict__ hidden) {
    int i = blockIdx.x * 256 + threadIdx.x;
    if (i < BATCH * HID) g_h[i] = hidden[i];
}

// ---------------- generic NT SGEMM: C[m,n] = sum_k A[m,k]*B[n,k] ----------------
// A,B row-major with row stride 1024 (all operands here have K-stride 1024).
// 64x64 block tile, BK=32, 256 threads, 4x4 microtile.
// blockIdx.z selects a K-chunk of length kLen starting at z*kLen; C advanced by
// z*cChunkStride (used by the split-K recurrence partial).
template<bool GATHER, int NBIAS>
__global__ void __launch_bounds__(256)
sgemm_nt64(const float* __restrict__ A, const float* __restrict__ B,
           float* __restrict__ C,
           const int* __restrict__ gidx,
           const float* __restrict__ bias0, const float* __restrict__ bias1,
           int kLen, int cChunkStride, int ldc)
{
    __shared__ __align__(16) float As[32][64];
    __shared__ __align__(16) float Bs[32][64];

    const int t  = threadIdx.x;
    const int m0 = blockIdx.y * 64;
    const int n0 = blockIdx.x * 64;
    const int k0 = blockIdx.z * kLen;
    float* Cz = C + (size_t)blockIdx.z * cChunkStride;

    // loader mapping: each thread loads 2 adjacent float4 of one row
    const int lrow = t >> 2;           // 0..63
    const int lkq  = (t & 3) * 2;      // 0,2,4,6  (float4 index within 32-wide k tile)

    long long arow;
    if (GATHER) arow = gidx[m0 + lrow];
    else        arow = m0 + lrow;
    const float* Arow = A + (size_t)arow * 1024 + k0 + lkq * 4;
    const float* Brow = B + (size_t)(n0 + lrow) * 1024 + k0 + lkq * 4;

    const int ty = t >> 4;             // 0..15
    const int tx = t & 15;             // 0..15

    float acc[4][4];
#pragma unroll
    for (int i = 0; i < 4; i++)
#pragma unroll
        for (int j = 0; j < 4; j++) acc[i][j] = 0.f;

    for (int kt = 0; kt < kLen; kt += 32) {
        float4 a0 = *(const float4*)(Arow + kt);
        float4 a1 = *(const float4*)(Arow + kt + 4);
        float4 b0 = *(const float4*)(Brow + kt);
        float4 b1 = *(const float4*)(Brow + kt + 4);
        __syncthreads();   // protect previous iteration's compute
        As[lkq * 4 + 0][lrow] = a0.x; As[lkq * 4 + 1][lrow] = a0.y;
        As[lkq * 4 + 2][lrow] = a0.z; As[lkq * 4 + 3][lrow] = a0.w;
        As[lkq * 4 + 4][lrow] = a1.x; As[lkq * 4 + 5][lrow] = a1.y;
        As[lkq * 4 + 6][lrow] = a1.z; As[lkq * 4 + 7][lrow] = a1.w;
        Bs[lkq * 4 + 0][lrow] = b0.x; Bs[lkq * 4 + 1][lrow] = b0.y;
        Bs[lkq * 4 + 2][lrow] = b0.z; Bs[lkq * 4 + 3][lrow] = b0.w;
        Bs[lkq * 4 + 4][lrow] = b1.x; Bs[lkq * 4 + 5][lrow] = b1.y;
        Bs[lkq * 4 + 6][lrow] = b1.z; Bs[lkq * 4 + 7][lrow] = b1.w;
        __syncthreads();
#pragma unroll
        for (int kk = 0; kk < 32; kk++) {
            float4 av = *(const float4*)&As[kk][ty * 4];
            float4 bv = *(const float4*)&Bs[kk][tx * 4];
            float ar[4] = {av.x, av.y, av.z, av.w};
            float br[4] = {bv.x, bv.y, bv.z, bv.w};
#pragma unroll
            for (int i = 0; i < 4; i++)
#pragma unroll
                for (int j = 0; j < 4; j++)
                    acc[i][j] += ar[i] * br[j];
        }
    }

#pragma unroll
    for (int i = 0; i < 4; i++) {
        int m = m0 + ty * 4 + i;
#pragma unroll
        for (int j = 0; j < 4; j++) {
            int n = n0 + tx * 4 + j;
            float v = acc[i][j];
            if (NBIAS >= 1) v += bias0[n];
            if (NBIAS >= 2) v += bias1[n];
            Cz[(size_t)m * ldc + n] = v;
        }
    }
}

// ---------------- recurrence reduce + tanh ----------------
__global__ void k_reduce_tanh(int s) {
    int i = blockIdx.x * 256 + threadIdx.x;   // 0..65535
    float v = g_xh[(size_t)s * BATCH * HID + i];
#pragma unroll
    for (int kc = 0; kc < KCH; kc++) v += g_part[kc * BATCH * HID + i];
    float h = tanhf(v);
    g_h[i] = h;
    g_hall[(size_t)s * BATCH * HID + i] = h;
}

__global__ void k_store_hidden(float* __restrict__ out) {
    int i = blockIdx.x * 256 + threadIdx.x;
    if (i < BATCH * HID) out[i] = g_h[i];
}

// ---------------- launch ----------------
extern "C" void kernel_launch(void* const* d_in, const int* in_sizes, int n_in,
                              void* d_out, int out_size)
{
    const void*  x      = d_in[0];
    const float* hidden = (const float*)d_in[1];
    const float* emb    = (const float*)d_in[2];
    const float* W_ih   = (const float*)d_in[3];
    const float* W_hh   = (const float*)d_in[4];
    const float* b_ih   = (const float*)d_in[5];
    const float* b_hh   = (const float*)d_in[6];
    const float* W_fc   = (const float*)d_in[7];
    const float* b_fc   = (const float*)d_in[8];
    float* out = (float*)d_out;

    float *p_xh, *p_hall, *p_h, *p_part;
    int* p_idx;
    cudaGetSymbolAddress((void**)&p_xh,   g_xh);
    cudaGetSymbolAddress((void**)&p_hall, g_hall);
    cudaGetSymbolAddress((void**)&p_h,    g_h);
    cudaGetSymbolAddress((void**)&p_part, g_part);
    cudaGetSymbolAddress((void**)&p_idx,  g_idx);

    k_sniff<<<1, 256>>>(x);
    k_decode<<<(SEQ * BATCH + 255) / 256, 256>>>(x);
    k_copyh<<<(BATCH * HID + 255) / 256, 256>>>(hidden);

    // xh = gather(emb) @ W_ih^T + b_ih + b_hh : M=8192, N=1024, K=1024
    sgemm_nt64<true, 2><<<dim3(HID / 64, (SEQ * BATCH) / 64, 1), 256>>>(
        emb, W_ih, p_xh, p_idx, b_ih, b_hh, HID, 0, HID);

    // recurrence: 128 sequential steps
    for (int s = 0; s < SEQ; s++) {
        // partial[kc][b][j] = sum_{k in chunk kc} h[b,k] * W_hh[j,k]
        sgemm_nt64<false, 0><<<dim3(HID / 64, 1, KCH), 256>>>(
            p_h, W_hh, p_part, nullptr, nullptr, nullptr,
            KC_LEN, BATCH * HID, HID);
        k_reduce_tanh<<<(BATCH * HID) / 256, 256>>>(s);
    }

    // outputs = g_hall @ W_fc^T + b_fc : M=8192, N=32000, K=1024
    sgemm_nt64<false, 1><<<dim3(OUT_DIM / 64, (SEQ * BATCH) / 64, 1), 256>>>(
        p_hall, W_fc, out, nullptr, b_fc, nullptr, HID, 0, OUT_DIM);

    // hidden_final appended after outputs
    k_store_hidden<<<(BATCH * HID) / 256, 256>>>(out + (size_t)SEQ * BATCH * OUT_DIM);
}

// round 3
// speedup vs baseline: 2.6467x; 2.6467x over previous
#include <cuda_runtime.h>
#include <cuda_bf16.h>
#include <cstdint>
#include <cstddef>

#define SEQ 128
#define BATCH 64
#define EMB 1024
#define HID 1024
#define OUT_DIM 32000
#define VOCAB 32000
#define KCH 8
#define KC_LEN (HID / KCH)

// big-GEMM (HMMA mma.sync) config
#define K2 3072                 // 3 segments of 1024 (hi/lo split-bf16)
#define BM 128
#define BN 128
#define BKK 32                  // k per stage (bf16 elems)
#define SROW 80                 // padded SMEM row stride in bytes (64B data + 16B pad)
#define STG_BYTES_TC (BM * SROW + BN * SROW)     // 20480
#define STAGES_TC 3
#define SMEM_TC (STAGES_TC * STG_BYTES_TC)       // 61440
#define NKT2 (K2 / BKK)         // 96
#define GH 16                   // m-block group height for L2-friendly ordering
#define NB (OUT_DIM / BN)       // 250

// ---------------- device scratch ----------------
__device__ __align__(16) float g_xh[SEQ * BATCH * HID];
__device__ __align__(16) float g_h[BATCH * HID];
__device__ __align__(16) float g_part[KCH * BATCH * HID];
__device__ __align__(16) __nv_bfloat16 g_hall2[SEQ * BATCH * K2];     // 48 MB
__device__ __align__(16) __nv_bfloat16 g_wfc2[OUT_DIM * K2];          // 192 MB
__device__ int g_idx[SEQ * BATCH];
__device__ int g_is64;

// ---------------- helpers ----------------
__device__ __forceinline__ uint32_t smem_u32(const void* p) {
    uint32_t a;
    asm("{ .reg .u64 t; cvta.to.shared.u64 t, %1; cvt.u32.u64 %0, t; }" : "=r"(a) : "l"(p));
    return a;
}
__device__ __forceinline__ void cp16(uint32_t s, const void* g) {
    asm volatile("cp.async.cg.shared.global [%0], [%1], 16;" :: "r"(s), "l"(g) : "memory");
}
__device__ __forceinline__ void ldmx4(uint32_t& r0, uint32_t& r1, uint32_t& r2, uint32_t& r3, uint32_t addr) {
    asm volatile("ldmatrix.sync.aligned.m8n8.x4.shared.b16 {%0,%1,%2,%3}, [%4];"
                 : "=r"(r0), "=r"(r1), "=r"(r2), "=r"(r3) : "r"(addr));
}
__device__ __forceinline__ void mma16816(float* c, const uint32_t* a, const uint32_t* b) {
    asm volatile("mma.sync.aligned.m16n8k16.row.col.f32.bf16.bf16.f32 "
                 "{%0,%1,%2,%3}, {%4,%5,%6,%7}, {%8,%9}, {%0,%1,%2,%3};"
                 : "+f"(c[0]), "+f"(c[1]), "+f"(c[2]), "+f"(c[3])
                 : "r"(a[0]), "r"(a[1]), "r"(a[2]), "r"(a[3]), "r"(b[0]), "r"(b[1]));
}

// ---------------- small kernels ----------------
__global__ void k_sniff(const void* x) {
    __shared__ int bad;
    if (threadIdx.x == 0) bad = 0;
    __syncthreads();
    const unsigned long long* p = (const unsigned long long*)x;
    int mybad = 0;
    for (int i = threadIdx.x; i < 4096; i += 256)
        if (p[i] >= (unsigned long long)VOCAB) mybad = 1;
    if (mybad) atomicOr(&bad, 1);
    __syncthreads();
    if (threadIdx.x == 0) g_is64 = bad ? 0 : 1;
}
__global__ void k_decode(const void* x) {
    int i = blockIdx.x * 256 + threadIdx.x;
    if (i >= SEQ * BATCH) return;
    if (g_is64) g_idx[i] = (int)((const long long*)x)[i];
    else        g_idx[i] = ((const int*)x)[i];
}
__global__ void k_copyh(const float* __restrict__ hidden) {
    int i = blockIdx.x * 256 + threadIdx.x;
    if (i < BATCH * HID) g_h[i] = hidden[i];
}
// W_fc fp32 -> split bf16 segments [hi | lo | hi]
__global__ void k_convw(const float* __restrict__ W) {
    int i = blockIdx.x * 256 + threadIdx.x;
    if (i >= OUT_DIM * HID) return;
    float v = W[i];
    __nv_bfloat16 hi = __float2bfloat16(v);
    __nv_bfloat16 lo = __float2bfloat16(v - __bfloat162float(hi));
    int row = i >> 10, k = i & 1023;
    size_t base = (size_t)row * K2 + k;
    g_wfc2[base] = hi;
    g_wfc2[base + 1024] = lo;
    g_wfc2[base + 2048] = hi;
}

// ---------------- fp32 SIMT NT SGEMM (xh + recurrence) ----------------
template<bool GATHER, int NBIAS>
__global__ void __launch_bounds__(256)
sgemm_nt64(const float* __restrict__ A, const float* __restrict__ B,
           float* __restrict__ C, const int* __restrict__ gidx,
           const float* __restrict__ bias0, const float* __restrict__ bias1,
           int kLen, int cChunkStride, int ldc)
{
    __shared__ __align__(16) float As[32][64];
    __shared__ __align__(16) float Bs[32][64];
    const int t = threadIdx.x;
    const int m0 = blockIdx.y * 64;
    const int n0 = blockIdx.x * 64;
    const int k0 = blockIdx.z * kLen;
    float* Cz = C + (size_t)blockIdx.z * cChunkStride;
    const int lrow = t >> 2;
    const int lkq = (t & 3) * 2;
    long long arow = GATHER ? (long long)gidx[m0 + lrow] : (long long)(m0 + lrow);
    const float* Arow = A + (size_t)arow * 1024 + k0 + lkq * 4;
    const float* Brow = B + (size_t)(n0 + lrow) * 1024 + k0 + lkq * 4;
    const int ty = t >> 4, tx = t & 15;
    float acc[4][4];
#pragma unroll
    for (int i = 0; i < 4; i++)
#pragma unroll
        for (int j = 0; j < 4; j++) acc[i][j] = 0.f;
    for (int kt = 0; kt < kLen; kt += 32) {
        float4 a0 = *(const float4*)(Arow + kt);
        float4 a1 = *(const float4*)(Arow + kt + 4);
        float4 b0 = *(const float4*)(Brow + kt);
        float4 b1 = *(const float4*)(Brow + kt + 4);
        __syncthreads();
        As[lkq * 4 + 0][lrow] = a0.x; As[lkq * 4 + 1][lrow] = a0.y;
        As[lkq * 4 + 2][lrow] = a0.z; As[lkq * 4 + 3][lrow] = a0.w;
        As[lkq * 4 + 4][lrow] = a1.x; As[lkq * 4 + 5][lrow] = a1.y;
        As[lkq * 4 + 6][lrow] = a1.z; As[lkq * 4 + 7][lrow] = a1.w;
        Bs[lkq * 4 + 0][lrow] = b0.x; Bs[lkq * 4 + 1][lrow] = b0.y;
        Bs[lkq * 4 + 2][lrow] = b0.z; Bs[lkq * 4 + 3][lrow] = b0.w;
        Bs[lkq * 4 + 4][lrow] = b1.x; Bs[lkq * 4 + 5][lrow] = b1.y;
        Bs[lkq * 4 + 6][lrow] = b1.z; Bs[lkq * 4 + 7][lrow] = b1.w;
        __syncthreads();
#pragma unroll
        for (int kk = 0; kk < 32; kk++) {
            float4 av = *(const float4*)&As[kk][ty * 4];
            float4 bv = *(const float4*)&Bs[kk][tx * 4];
            float ar[4] = {av.x, av.y, av.z, av.w};
            float br[4] = {bv.x, bv.y, bv.z, bv.w};
#pragma unroll
            for (int i = 0; i < 4; i++)
#pragma unroll
                for (int j = 0; j < 4; j++) acc[i][j] += ar[i] * br[j];
        }
    }
#pragma unroll
    for (int i = 0; i < 4; i++) {
        int m = m0 + ty * 4 + i;
#pragma unroll
        for (int j = 0; j < 4; j++) {
            int n = n0 + tx * 4 + j;
            float v = acc[i][j];
            if (NBIAS >= 1) v += bias0[n];
            if (NBIAS >= 2) v += bias1[n];
            Cz[(size_t)m * ldc + n] = v;
        }
    }
}

// ---------------- recurrence reduce + tanh + bf16 split emit ----------------
__global__ void k_reduce_tanh(int s) {
    int i = blockIdx.x * 256 + threadIdx.x;
    float v = g_xh[(size_t)s * BATCH * HID + i];
#pragma unroll
    for (int kc = 0; kc < KCH; kc++) v += g_part[kc * BATCH * HID + i];
    float h = tanhf(v);
    g_h[i] = h;
    __nv_bfloat16 hi = __float2bfloat16(h);
    __nv_bfloat16 lo = __float2bfloat16(h - __bfloat162float(hi));
    int b = i >> 10, j = i & 1023;
    size_t base = (size_t)(s * BATCH + b) * K2 + j;
    g_hall2[base] = hi;          // seg0: hi (pairs with w hi)
    g_hall2[base + 1024] = hi;   // seg1: hi (pairs with w lo)
    g_hall2[base + 2048] = lo;   // seg2: lo (pairs with w hi)
}

__global__ void k_store_hidden(float* __restrict__ out) {
    int i = blockIdx.x * 256 + threadIdx.x;
    if (i < BATCH * HID) out[i] = g_h[i];
}

// ---------------- HMMA bf16 GEMM: C[8192,32000] = A2 @ B2^T + bias ----------------
__global__ void __launch_bounds__(256, 2)
gemm_tc(const __nv_bfloat16* __restrict__ A2, const __nv_bfloat16* __restrict__ B2,
        float* __restrict__ C, const float* __restrict__ bias)
{
    extern __shared__ __align__(16) char smem[];
    const uint32_t sBase = smem_u32(smem);
    const int t = threadIdx.x;
    const int lane = t & 31, wid = t >> 5;
    const int warp_m = wid & 1;      // 2 warps along M (64 rows each)
    const int warp_n = wid >> 1;     // 4 warps along N (32 cols each)

    // block swizzle: groups of GH m-blocks sweep all n (A stays in L2)
    int bid = blockIdx.x;
    int group = bid / (GH * NB);
    int rem = bid % (GH * NB);
    int m0 = (group * GH + rem % GH) * BM;
    int n0 = (rem / GH) * BN;

    // cp.async slots: 2 x 16B chunks per thread per operand
    uint32_t soffA[2], soffB[2];
    const char *gA[2], *gB[2];
#pragma unroll
    for (int i = 0; i < 2; i++) {
        int c = t + 256 * i;
        int row = c >> 2, q = c & 3;
        soffA[i] = (uint32_t)(row * SROW + q * 16);
        soffB[i] = (uint32_t)(BM * SROW + row * SROW + q * 16);
        gA[i] = (const char*)A2 + (size_t)(m0 + row) * (K2 * 2) + q * 16;
        gB[i] = (const char*)B2 + (size_t)(n0 + row) * (K2 * 2) + q * 16;
    }

    // ldmatrix per-lane offsets (relative to stage base)
    const int arow = ((lane >> 3) & 1) * 8 + (lane & 7);
    const int ahalf = (lane >> 4) & 1;
    const uint32_t aOff = (uint32_t)((warp_m * 64 + arow) * SROW + ahalf * 16);
    const int brow = ((lane >> 4) & 1) * 8 + (lane & 7);
    const int bhalf = (lane >> 3) & 1;
    const uint32_t bOff = (uint32_t)(BM * SROW + (warp_n * 32 + brow) * SROW + bhalf * 16);

    float acc[4][4][4];
#pragma unroll
    for (int mt = 0; mt < 4; mt++)
#pragma unroll
        for (int nt = 0; nt < 4; nt++)
#pragma unroll
            for (int e = 0; e < 4; e++) acc[mt][nt][e] = 0.f;

    // prologue: stages 0,1
#pragma unroll
    for (int p = 0; p < STAGES_TC - 1; p++) {
        uint32_t stg = sBase + p * STG_BYTES_TC;
        size_t koff = (size_t)p * (BKK * 2);
#pragma unroll
        for (int i = 0; i < 2; i++) cp16(stg + soffA[i], gA[i] + koff);
#pragma unroll
        for (int i = 0; i < 2; i++) cp16(stg + soffB[i], gB[i] + koff);
        asm volatile("cp.async.commit_group;" ::: "memory");
    }

    for (int kt = 0; kt < NKT2; kt++) {
        if (kt < NKT2 - 1) asm volatile("cp.async.wait_group 1;" ::: "memory");
        else               asm volatile("cp.async.wait_group 0;" ::: "memory");
        __syncthreads();

        // prefetch kt+2 into the slot freed by kt-1
        if (kt + 2 < NKT2) {
            uint32_t stg2 = sBase + ((kt + 2) % STAGES_TC) * STG_BYTES_TC;
            size_t koff = (size_t)(kt + 2) * (BKK * 2);
#pragma unroll
            for (int i = 0; i < 2; i++) cp16(stg2 + soffA[i], gA[i] + koff);
#pragma unroll
            for (int i = 0; i < 2; i++) cp16(stg2 + soffB[i], gB[i] + koff);
            asm volatile("cp.async.commit_group;" ::: "memory");
        }

        const uint32_t stg = sBase + (kt % STAGES_TC) * STG_BYTES_TC;
#pragma unroll
        for (int kp = 0; kp < 2; kp++) {
            uint32_t af[4][4], bf[2][4];
#pragma unroll
            for (int mt = 0; mt < 4; mt++)
                ldmx4(af[mt][0], af[mt][1], af[mt][2], af[mt][3],
                      stg + aOff + mt * 16 * SROW + kp * 32);
#pragma unroll
            for (int p = 0; p < 2; p++)
                ldmx4(bf[p][0], bf[p][1], bf[p][2], bf[p][3],
                      stg + bOff + p * 16 * SROW + kp * 32);
#pragma unroll
            for (int mt = 0; mt < 4; mt++)
#pragma unroll
                for (int nt = 0; nt < 4; nt++)
                    mma16816(acc[mt][nt], af[mt], &bf[nt >> 1][(nt & 1) * 2]);
        }
    }

    // epilogue: direct global stores + bias
#pragma unroll
    for (int mt = 0; mt < 4; mt++) {
        int row = m0 + warp_m * 64 + mt * 16 + (lane >> 2);
#pragma unroll
        for (int nt = 0; nt < 4; nt++) {
            int col = n0 + warp_n * 32 + nt * 8 + (lane & 3) * 2;
            float b0 = __ldg(&bias[col]), b1 = __ldg(&bias[col + 1]);
            float2 v0 = make_float2(acc[mt][nt][0] + b0, acc[mt][nt][1] + b1);
            float2 v1 = make_float2(acc[mt][nt][2] + b0, acc[mt][nt][3] + b1);
            *(float2*)&C[(size_t)row * OUT_DIM + col] = v0;
            *(float2*)&C[(size_t)(row + 8) * OUT_DIM + col] = v1;
        }
    }
}

// ---------------- launch ----------------
extern "C" void kernel_launch(void* const* d_in, const int* in_sizes, int n_in,
                              void* d_out, int out_size)
{
    const void*  x      = d_in[0];
    const float* hidden = (const float*)d_in[1];
    const float* emb    = (const float*)d_in[2];
    const float* W_ih   = (const float*)d_in[3];
    const float* W_hh   = (const float*)d_in[4];
    const float* b_ih   = (const float*)d_in[5];
    const float* b_hh   = (const float*)d_in[6];
    const float* W_fc   = (const float*)d_in[7];
    const float* b_fc   = (const float*)d_in[8];
    float* out = (float*)d_out;

    float *p_xh, *p_h, *p_part;
    __nv_bfloat16 *p_hall2, *p_wfc2;
    int* p_idx;
    cudaGetSymbolAddress((void**)&p_xh,    g_xh);
    cudaGetSymbolAddress((void**)&p_h,     g_h);
    cudaGetSymbolAddress((void**)&p_part,  g_part);
    cudaGetSymbolAddress((void**)&p_hall2, g_hall2);
    cudaGetSymbolAddress((void**)&p_wfc2,  g_wfc2);
    cudaGetSymbolAddress((void**)&p_idx,   g_idx);

    cudaFuncSetAttribute(gemm_tc, cudaFuncAttributeMaxDynamicSharedMemorySize, SMEM_TC);

    k_sniff<<<1, 256>>>(x);
    k_decode<<<(SEQ * BATCH + 255) / 256, 256>>>(x);
    k_copyh<<<(BATCH * HID + 255) / 256, 256>>>(hidden);
    k_convw<<<(OUT_DIM * HID) / 256, 256>>>(W_fc);

    // xh = gather(emb) @ W_ih^T + b_ih + b_hh
    sgemm_nt64<true, 2><<<dim3(HID / 64, (SEQ * BATCH) / 64, 1), 256>>>(
        emb, W_ih, p_xh, p_idx, b_ih, b_hh, HID, 0, HID);

    // recurrence
    for (int s = 0; s < SEQ; s++) {
        sgemm_nt64<false, 0><<<dim3(HID / 64, 1, KCH), 256>>>(
            p_h, W_hh, p_part, nullptr, nullptr, nullptr,
            KC_LEN, BATCH * HID, HID);
        k_reduce_tanh<<<(BATCH * HID) / 256, 256>>>(s);
    }

    // outputs = hall2 @ wfc2^T (split-bf16, 3 terms) + b_fc
    gemm_tc<<<GH * NB * ((SEQ * BATCH) / (BM * GH)), 256, SMEM_TC>>>(
        p_hall2, p_wfc2, out, b_fc);

    k_store_hidden<<<(BATCH * HID + 255) / 256, 256>>>(out + (size_t)SEQ * BATCH * OUT_DIM);
}